// round 15
// baseline (speedup 1.0000x reference)
#include <cuda_runtime.h>
#include <cstdint>

#define BB 8
#define CC 128
#define NN 4096
#define KK 8
#define TM 128
#define TN 64

// ---- device scratch (no allocations allowed) ----
__device__ float g_xx[BB * NN];
__device__ int   g_idx[BB * NN * KK];
__device__ float g_G[(size_t)BB * CC * NN];
__device__ float g_WT[CC * CC];
__device__ float g_PT[(size_t)BB * NN * CC];   // points transposed: [b][n][c]

__device__ __forceinline__ float lrelu(float x) { return x > 0.f ? x : 0.01f * x; }

extern __shared__ __align__(16) float smem[];

// ---------------- xx[b,n] = sum_c points^2 ----------------
__global__ void xx_kernel(const float* __restrict__ pts) {
    int t = blockIdx.x * blockDim.x + threadIdx.x;   // b*N + n
    int b = t >> 12, n = t & (NN - 1);
    const float* p = pts + (size_t)b * CC * NN + n;
    float s = 0.f;
#pragma unroll
    for (int c = 0; c < CC; c++) { float v = p[(size_t)c * NN]; s = fmaf(v, v, s); }
    g_xx[t] = s;
}

// ---------------- transpose conv2_w -> g_WT[c][o] ----------------
__global__ void wt_kernel(const float* __restrict__ w) {
    int t = blockIdx.x * blockDim.x + threadIdx.x;   // o*128 + c
    int o = t >> 7, c = t & 127;
    g_WT[c * CC + o] = w[t];
}

// ---------------- transpose points -> g_PT[b][n][c] ----------------
__global__ void pt_kernel(const float* __restrict__ pts) {
    __shared__ float t[32][33];
    int b  = blockIdx.z;
    int c0 = blockIdx.y * 32, n0 = blockIdx.x * 32;
    for (int i = threadIdx.y; i < 32; i += 8)
        t[i][threadIdx.x] = pts[(size_t)b * CC * NN + (size_t)(c0 + i) * NN + n0 + threadIdx.x];
    __syncthreads();
    for (int i = threadIdx.y; i < 32; i += 8)
        g_PT[((size_t)b * NN + n0 + i) * CC + c0 + threadIdx.x] = t[threadIdx.x][i];
}

// ---------------- fused Gram + top-8 (the hot kernel) ----------------
// 128 threads/CTA, 2 CTAs/SM. Thread = 8 rows (rg*4+{0..3} and 64+rg*4+{0..3})
// x 8 cols (cg*8..cg*8+7). A loaded as 2 conflict-free ld.shared.v2.b64 giving
// NATURAL row-pairs for FFMA2 (no A packs); B via 2 broadcast ld.shared.v4.b32
// + 8 dup packs. Per-(row,col) accumulation chain over k and the score
// expression 2*inner - xr - xc are bit-identical to the verified round-6
// kernel, so fp32 selection decisions match the reference's top_k everywhere.
#define FMA2(ACC, A, Bv) asm("fma.rn.f32x2 %0,%1,%2,%0;" : "+l"(ACC) : "l"(A), "l"(Bv))

#define SMEM_FLOATS (CC * TM + CC * TN + 32 * 128)   // 28672 floats = 112KB

__global__ void __launch_bounds__(128, 2) gram_topk_kernel(const float* __restrict__ pts) {
    float* As = smem;                 // [k][r] 128x128 = 64KB
    float* Bs = As + CC * TM;         // [k][c] 128x64  = 32KB
    float* Ss = Bs + CC * TN;         // [32][128] col-major chunk = 16KB

    const int tid  = threadIdx.x;
    const int rg   = tid & 15;        // row group
    const int cg   = tid >> 4;        // col group (0..7)
    const int ra   = rg * 4;          // rows ra..ra+3
    const int rb   = 64 + rg * 4;     // rows rb..rb+3
    const int c0   = cg * 8;          // cols c0..c0+7
    const int chunkq  = cg >> 2;      // which 32-col chunk this thread stages
    const int clcBase = (cg & 3) * 8; // col offset within chunk

    const int b    = blockIdx.y;
    const int row0 = blockIdx.x * TM;
    const float* P = pts + (size_t)b * CC * NN;

    // Load A tile once (coalesced, k-major, rows contiguous)
    for (int i = tid; i < CC * TM / 4; i += 128) {
        int k = i >> 5, r4 = (i & 31) << 2;
        *(float4*)(As + k * TM + r4) = *(const float4*)(P + (size_t)k * NN + row0 + r4);
    }

    // row norms for this thread's 8 rows
    float4 xra = *(const float4*)(g_xx + b * NN + row0 + ra);
    float4 xrb = *(const float4*)(g_xx + b * NN + row0 + rb);

    // per-thread sorted top-8 (thread owns row row0+tid for the scan)
    float sc[KK]; int ix[KK];
#pragma unroll
    for (int p = 0; p < KK; p++) { sc[p] = -3e38f; ix[p] = 0; }

    unsigned aAddr = (unsigned)__cvta_generic_to_shared(As) + rg * 16;
    unsigned bAddr = (unsigned)__cvta_generic_to_shared(Bs) + cg * 32;

    for (int ct = 0; ct < NN / TN; ct++) {
        const int col0 = ct * TN;

        for (int i = tid; i < CC * TN / 4; i += 128) {
            int k = i >> 4, c4 = (i & 15) << 2;
            *(float4*)(Bs + k * TN + c4) = *(const float4*)(P + (size_t)k * NN + col0 + c4);
        }
        __syncthreads();

        // col norms for this thread's 8 cols (hidden under compute)
        float4 xq0 = *(const float4*)(g_xx + b * NN + col0 + c0);
        float4 xq1 = *(const float4*)(g_xx + b * NN + col0 + c0 + 4);

        unsigned long long acc[32];   // acc[p*8+j]: row-pair p, col c0+j
#pragma unroll
        for (int i = 0; i < 32; i++) acc[i] = 0ULL;

#pragma unroll 4
        for (int k = 0; k < CC; k++) {
            unsigned long long A0, A1, A2, A3;
            asm volatile("ld.shared.v2.b64 {%0,%1},[%2];"
                         : "=l"(A0), "=l"(A1) : "r"(aAddr + k * (TM * 4)));
            asm volatile("ld.shared.v2.b64 {%0,%1},[%2];"
                         : "=l"(A2), "=l"(A3) : "r"(aAddr + k * (TM * 4) + 256));
            float b0, b1, b2, b3, b4, b5, b6, b7;
            asm volatile("ld.shared.v4.b32 {%0,%1,%2,%3},[%4];"
                         : "=f"(b0), "=f"(b1), "=f"(b2), "=f"(b3)
                         : "r"(bAddr + k * (TN * 4)));
            asm volatile("ld.shared.v4.b32 {%0,%1,%2,%3},[%4];"
                         : "=f"(b4), "=f"(b5), "=f"(b6), "=f"(b7)
                         : "r"(bAddr + k * (TN * 4) + 16));
            unsigned long long Bd[8];
            asm("mov.b64 %0,{%1,%1};" : "=l"(Bd[0]) : "f"(b0));
            asm("mov.b64 %0,{%1,%1};" : "=l"(Bd[1]) : "f"(b1));
            asm("mov.b64 %0,{%1,%1};" : "=l"(Bd[2]) : "f"(b2));
            asm("mov.b64 %0,{%1,%1};" : "=l"(Bd[3]) : "f"(b3));
            asm("mov.b64 %0,{%1,%1};" : "=l"(Bd[4]) : "f"(b4));
            asm("mov.b64 %0,{%1,%1};" : "=l"(Bd[5]) : "f"(b5));
            asm("mov.b64 %0,{%1,%1};" : "=l"(Bd[6]) : "f"(b6));
            asm("mov.b64 %0,{%1,%1};" : "=l"(Bd[7]) : "f"(b7));
#pragma unroll
            for (int j = 0; j < 8; j++) {
                FMA2(acc[0 * 8 + j], A0, Bd[j]);
                FMA2(acc[1 * 8 + j], A1, Bd[j]);
                FMA2(acc[2 * 8 + j], A2, Bd[j]);
                FMA2(acc[3 * 8 + j], A3, Bd[j]);
            }
        }

        // two 32-col chunks; threads with chunkq==q stage their 8 cols
#pragma unroll
        for (int q = 0; q < 2; q++) {
            if (chunkq == q) {
#pragma unroll
                for (int j = 0; j < 8; j++) {
                    float lo0, hi0, lo1, hi1, lo2, hi2, lo3, hi3;
                    asm("mov.b64 {%0,%1},%2;" : "=f"(lo0), "=f"(hi0) : "l"(acc[0 * 8 + j]));
                    asm("mov.b64 {%0,%1},%2;" : "=f"(lo1), "=f"(hi1) : "l"(acc[1 * 8 + j]));
                    asm("mov.b64 {%0,%1},%2;" : "=f"(lo2), "=f"(hi2) : "l"(acc[2 * 8 + j]));
                    asm("mov.b64 {%0,%1},%2;" : "=f"(lo3), "=f"(hi3) : "l"(acc[3 * 8 + j]));
                    float xc;
                    if (j == 0) xc = xq0.x; else if (j == 1) xc = xq0.y;
                    else if (j == 2) xc = xq0.z; else if (j == 3) xc = xq0.w;
                    else if (j == 4) xc = xq1.x; else if (j == 5) xc = xq1.y;
                    else if (j == 6) xc = xq1.z; else xc = xq1.w;
                    // EXACT score expression (matches reference noise):
                    float4 va = make_float4(2.f * lo0 - xra.x - xc, 2.f * hi0 - xra.y - xc,
                                            2.f * lo1 - xra.z - xc, 2.f * hi1 - xra.w - xc);
                    float4 vb = make_float4(2.f * lo2 - xrb.x - xc, 2.f * hi2 - xrb.y - xc,
                                            2.f * lo3 - xrb.z - xc, 2.f * hi3 - xrb.w - xc);
                    *(float4*)(Ss + (clcBase + j) * 128 + ra) = va;   // conflict-free
                    *(float4*)(Ss + (clcBase + j) * 128 + rb) = vb;
                }
            }
            __syncthreads();

            // scan: each thread scans its row over the 32 staged cols,
            // ascending column order (preserves lower-index-on-tie semantics)
            {
                const int cbase = col0 + q * 32;
#pragma unroll 4
                for (int j = 0; j < 32; j++) {
                    float s = Ss[j * 128 + tid];
                    if (s > sc[KK - 1]) {
                        int idv = cbase + j;
#pragma unroll
                        for (int p = KK - 1; p >= 1; --p) {
                            bool up  = s > sc[p - 1];
                            float ns = up ? sc[p - 1] : ((s > sc[p]) ? s   : sc[p]);
                            int   ni = up ? ix[p - 1] : ((s > sc[p]) ? idv : ix[p]);
                            sc[p] = ns; ix[p] = ni;
                        }
                        if (s > sc[0]) { sc[0] = s; ix[0] = idv; }
                    }
                }
            }
            __syncthreads();
        }
    }

    {
        size_t base = ((size_t)b * NN + row0 + tid) * KK;
#pragma unroll
        for (int p = 0; p < KK; p++) g_idx[base + p] = ix[p];
    }
}

// ---------------- fp64 exact rescoring of the 8 selected -> true order ----------------
__global__ void refine_kernel() {
    int b    = blockIdx.y;
    int n    = blockIdx.x * 8 + (threadIdx.x >> 5);
    int lane = threadIdx.x & 31;

    const float* ct = g_PT + ((size_t)b * NN + n) * CC;
    float cn[4];
#pragma unroll
    for (int i = 0; i < 4; i++) cn[i] = ct[lane + 32 * i];

    int* ip = g_idx + ((size_t)b * NN + n) * KK;
    double d[KK]; int id[KK];
#pragma unroll
    for (int k = 0; k < KK; k++) {
        int j = ip[k]; id[k] = j;
        const float* nt = g_PT + ((size_t)b * NN + j) * CC;
        double s = 0.0;
#pragma unroll
        for (int i = 0; i < 4; i++) {
            double df = (double)cn[i] - (double)nt[lane + 32 * i];
            s += df * df;
        }
#pragma unroll
        for (int o = 16; o > 0; o >>= 1) s += __shfl_xor_sync(0xffffffffu, s, o);
        d[k] = s;
    }

    if (lane == 0) {
        // insertion sort ascending by (d, idx): matches jax top_k ordering
        for (int a = 1; a < KK; a++) {
            double dv = d[a]; int iv = id[a]; int p = a - 1;
            while (p >= 0 && (d[p] > dv || (d[p] == dv && id[p] > iv))) {
                d[p + 1] = d[p]; id[p + 1] = id[p]; p--;
            }
            d[p + 1] = dv; id[p + 1] = iv;
        }
#pragma unroll
        for (int k = 0; k < KK; k++) ip[k] = id[k];
    }
}

// ---------------- G = conv2_w @ lrelu(points)  (per batch 128x4096x128) ----------------
__global__ void __launch_bounds__(256, 1) ggemm_kernel(const float* __restrict__ pts) {
    float* Ws = smem;              // [c][o] 128x128
    float* Fs = Ws + CC * CC;      // [c][n] 128x128
    const int tid = threadIdx.x;
    const int b = blockIdx.y;
    const int n0 = blockIdx.x * 128;
    const float* P = pts + (size_t)b * CC * NN;

    for (int i = tid; i < CC * CC / 4; i += 256)
        *(float4*)(Ws + i * 4) = *(const float4*)(g_WT + i * 4);
    for (int i = tid; i < CC * 128 / 4; i += 256) {
        int c = i >> 5; int n4 = (i & 31) << 2;
        float4 v = *(const float4*)(P + (size_t)c * NN + n0 + n4);
        v.x = lrelu(v.x); v.y = lrelu(v.y); v.z = lrelu(v.z); v.w = lrelu(v.w);
        *(float4*)(Fs + c * 128 + n4) = v;
    }
    __syncthreads();

    const int o0 = (tid & 15) * 8;
    const int m0 = (tid >> 4) * 8;
    float acc[8][8];
#pragma unroll
    for (int i = 0; i < 8; i++)
#pragma unroll
        for (int j = 0; j < 8; j++) acc[i][j] = 0.f;

#pragma unroll 2
    for (int k = 0; k < CC; k++) {
        float4 a0 = *(float4*)(Ws + k * CC + o0);
        float4 a1 = *(float4*)(Ws + k * CC + o0 + 4);
        float4 f0 = *(float4*)(Fs + k * 128 + m0);
        float4 f1 = *(float4*)(Fs + k * 128 + m0 + 4);
        float a[8] = { a0.x, a0.y, a0.z, a0.w, a1.x, a1.y, a1.z, a1.w };
        float f[8] = { f0.x, f0.y, f0.z, f0.w, f1.x, f1.y, f1.z, f1.w };
#pragma unroll
        for (int i = 0; i < 8; i++)
#pragma unroll
            for (int j = 0; j < 8; j++) acc[i][j] = fmaf(a[i], f[j], acc[i][j]);
    }

    float* Gp = g_G + (size_t)b * CC * NN;
#pragma unroll
    for (int i = 0; i < 8; i++) {
        float4 v0 = make_float4(acc[i][0], acc[i][1], acc[i][2], acc[i][3]);
        float4 v1 = make_float4(acc[i][4], acc[i][5], acc[i][6], acc[i][7]);
        *(float4*)(Gp + (size_t)(o0 + i) * NN + n0 + m0)     = v0;
        *(float4*)(Gp + (size_t)(o0 + i) * NN + n0 + m0 + 4) = v1;
    }
}

// ---------------- fused: out[b,c,n] and gnn[b,c,n,k] ----------------
// out = points + (lrelu(center) + sum_k lrelu(nbr))/9 ;  gnn = G[b,c,idx[b,n,k]]
__global__ void outgnn_kernel(const float* __restrict__ pts,
                              float* __restrict__ out, float* __restrict__ gnn) {
    __shared__ float prow[NN];
    __shared__ float grow[NN];
    int b = blockIdx.y, c = blockIdx.x;
    const float* P  = pts + ((size_t)b * CC + c) * NN;
    const float* Gp = g_G + ((size_t)b * CC + c) * NN;
    for (int i = threadIdx.x; i < NN / 4; i += 256) {
        *(float4*)(prow + i * 4) = *(const float4*)(P + i * 4);
        *(float4*)(grow + i * 4) = *(const float4*)(Gp + i * 4);
    }
    __syncthreads();
    float* gdst = gnn + ((size_t)b * CC + c) * NN * KK;
    for (int n = threadIdx.x; n < NN; n += 256) {
        const int4* ip = (const int4*)(g_idx + ((size_t)b * NN + n) * 8);
        int4 i0 = ip[0], i1 = ip[1];
        float x = prow[n];
        float s = lrelu(x);
        s += lrelu(prow[i0.x]); s += lrelu(prow[i0.y]); s += lrelu(prow[i0.z]); s += lrelu(prow[i0.w]);
        s += lrelu(prow[i1.x]); s += lrelu(prow[i1.y]); s += lrelu(prow[i1.z]); s += lrelu(prow[i1.w]);
        out[((size_t)b * CC + c) * NN + n] = x + s * (1.f / 9.f);
        float4 g0 = make_float4(grow[i0.x], grow[i0.y], grow[i0.z], grow[i0.w]);
        float4 g1 = make_float4(grow[i1.x], grow[i1.y], grow[i1.z], grow[i1.w]);
        *(float4*)(gdst + (size_t)n * KK)     = g0;
        *(float4*)(gdst + (size_t)n * KK + 4) = g1;
    }
}

// ---------------- launch ----------------
extern "C" void kernel_launch(void* const* d_in, const int* in_sizes, int n_in,
                              void* d_out, int out_size) {
    (void)in_sizes; (void)n_in; (void)out_size;
    const float* pts    = (const float*)d_in[0];
    // d_in[1] (W) is provably unused: mean(softmax) == 1/9 exactly.
    const float* conv2w = (const float*)d_in[2];
    float* out = (float*)d_out;
    float* gnn = out + (size_t)BB * CC * NN;

    cudaFuncSetAttribute(gram_topk_kernel, cudaFuncAttributeMaxDynamicSharedMemorySize, SMEM_FLOATS * 4);
    cudaFuncSetAttribute(ggemm_kernel,     cudaFuncAttributeMaxDynamicSharedMemorySize, 131072);

    xx_kernel<<<BB * NN / 256, 256>>>(pts);
    wt_kernel<<<CC * CC / 256, 256>>>(conv2w);
    pt_kernel<<<dim3(NN / 32, CC / 32, BB), dim3(32, 8)>>>(pts);
    gram_topk_kernel<<<dim3(NN / TM, BB), 128, SMEM_FLOATS * 4>>>(pts);
    refine_kernel<<<dim3(NN / 8, BB), 256>>>();
    ggemm_kernel<<<dim3(NN / 128, BB), 256, 131072>>>(pts);
    outgnn_kernel<<<dim3(CC, BB), 256>>>(pts, out, gnn);
}

// round 16
// speedup vs baseline: 1.0019x; 1.0019x over previous
#include <cuda_runtime.h>
#include <cstdint>

#define BB 8
#define CC 128
#define NN 4096
#define KK 8
#define TM 128
#define TN 64

// ---- device scratch (no allocations allowed) ----
__device__ float g_xx[BB * NN];
__device__ int   g_idx[BB * NN * KK];
__device__ float g_G[(size_t)BB * CC * NN];
__device__ float g_WT[CC * CC];
__device__ float g_PT[(size_t)BB * NN * CC];   // points transposed: [b][n][c]

__device__ __forceinline__ float lrelu(float x) { return x > 0.f ? x : 0.01f * x; }

extern __shared__ __align__(16) float smem[];

// ---------------- xx[b,n] = sum_c points^2 ----------------
__global__ void xx_kernel(const float* __restrict__ pts) {
    int t = blockIdx.x * blockDim.x + threadIdx.x;   // b*N + n
    int b = t >> 12, n = t & (NN - 1);
    const float* p = pts + (size_t)b * CC * NN + n;
    float s = 0.f;
#pragma unroll
    for (int c = 0; c < CC; c++) { float v = p[(size_t)c * NN]; s = fmaf(v, v, s); }
    g_xx[t] = s;
}

// ---------------- transpose conv2_w -> g_WT[c][o] ----------------
__global__ void wt_kernel(const float* __restrict__ w) {
    int t = blockIdx.x * blockDim.x + threadIdx.x;   // o*128 + c
    int o = t >> 7, c = t & 127;
    g_WT[c * CC + o] = w[t];
}

// ---------------- transpose points -> g_PT[b][n][c] ----------------
__global__ void pt_kernel(const float* __restrict__ pts) {
    __shared__ float t[32][33];
    int b  = blockIdx.z;
    int c0 = blockIdx.y * 32, n0 = blockIdx.x * 32;
    for (int i = threadIdx.y; i < 32; i += 8)
        t[i][threadIdx.x] = pts[(size_t)b * CC * NN + (size_t)(c0 + i) * NN + n0 + threadIdx.x];
    __syncthreads();
    for (int i = threadIdx.y; i < 32; i += 8)
        g_PT[((size_t)b * NN + n0 + i) * CC + c0 + threadIdx.x] = t[threadIdx.x][i];
}

// ---------------- fused Gram + top-8 (the hot kernel) ----------------
// 128 threads/CTA, 2 CTAs/SM. Thread = 8 rows (rg*4+{0..3} and 64+rg*4+{0..3})
// x 8 cols (cg*8..cg*8+7). A loaded as 2 conflict-free ld.shared.v2.b64 giving
// NATURAL row-pairs for FFMA2 (no A packs); B via 2 broadcast ld.shared.v4.b32
// + 8 dup packs. Per-(row,col) accumulation chain over k and the score
// expression 2*inner - xr - xc are bit-identical to the verified round-6
// kernel, so fp32 selection decisions match the reference's top_k everywhere.
#define FMA2(ACC, A, Bv) asm("fma.rn.f32x2 %0,%1,%2,%0;" : "+l"(ACC) : "l"(A), "l"(Bv))

#define SMEM_FLOATS (CC * TM + CC * TN + 32 * 128)   // 28672 floats = 112KB

__global__ void __launch_bounds__(128, 2) gram_topk_kernel(const float* __restrict__ pts) {
    float* As = smem;                 // [k][r] 128x128 = 64KB
    float* Bs = As + CC * TM;         // [k][c] 128x64  = 32KB
    float* Ss = Bs + CC * TN;         // [32][128] col-major chunk = 16KB

    const int tid  = threadIdx.x;
    const int rg   = tid & 15;        // row group
    const int cg   = tid >> 4;        // col group (0..7)
    const int ra   = rg * 4;          // rows ra..ra+3
    const int rb   = 64 + rg * 4;     // rows rb..rb+3
    const int c0   = cg * 8;          // cols c0..c0+7
    const int chunkq  = cg >> 2;      // which 32-col chunk this thread stages
    const int clcBase = (cg & 3) * 8; // col offset within chunk

    const int b    = blockIdx.y;
    const int row0 = blockIdx.x * TM;
    const float* P = pts + (size_t)b * CC * NN;

    // Load A tile once (coalesced, k-major, rows contiguous)
    for (int i = tid; i < CC * TM / 4; i += 128) {
        int k = i >> 5, r4 = (i & 31) << 2;
        *(float4*)(As + k * TM + r4) = *(const float4*)(P + (size_t)k * NN + row0 + r4);
    }

    // row norms for this thread's 8 rows
    float4 xra = *(const float4*)(g_xx + b * NN + row0 + ra);
    float4 xrb = *(const float4*)(g_xx + b * NN + row0 + rb);

    // per-thread sorted top-8 (thread owns row row0+tid for the scan)
    float sc[KK]; int ix[KK];
#pragma unroll
    for (int p = 0; p < KK; p++) { sc[p] = -3e38f; ix[p] = 0; }

    unsigned aAddr = (unsigned)__cvta_generic_to_shared(As) + rg * 16;
    unsigned bAddr = (unsigned)__cvta_generic_to_shared(Bs) + cg * 32;

    for (int ct = 0; ct < NN / TN; ct++) {
        const int col0 = ct * TN;

        for (int i = tid; i < CC * TN / 4; i += 128) {
            int k = i >> 4, c4 = (i & 15) << 2;
            *(float4*)(Bs + k * TN + c4) = *(const float4*)(P + (size_t)k * NN + col0 + c4);
        }
        __syncthreads();

        // col norms for this thread's 8 cols (hidden under compute)
        float4 xq0 = *(const float4*)(g_xx + b * NN + col0 + c0);
        float4 xq1 = *(const float4*)(g_xx + b * NN + col0 + c0 + 4);

        unsigned long long acc[32];   // acc[p*8+j]: row-pair p, col c0+j
#pragma unroll
        for (int i = 0; i < 32; i++) acc[i] = 0ULL;

#pragma unroll 4
        for (int k = 0; k < CC; k++) {
            unsigned long long A0, A1, A2, A3;
            asm volatile("ld.shared.v2.b64 {%0,%1},[%2];"
                         : "=l"(A0), "=l"(A1) : "r"(aAddr + k * (TM * 4)));
            asm volatile("ld.shared.v2.b64 {%0,%1},[%2];"
                         : "=l"(A2), "=l"(A3) : "r"(aAddr + k * (TM * 4) + 256));
            float b0, b1, b2, b3, b4, b5, b6, b7;
            asm volatile("ld.shared.v4.b32 {%0,%1,%2,%3},[%4];"
                         : "=f"(b0), "=f"(b1), "=f"(b2), "=f"(b3)
                         : "r"(bAddr + k * (TN * 4)));
            asm volatile("ld.shared.v4.b32 {%0,%1,%2,%3},[%4];"
                         : "=f"(b4), "=f"(b5), "=f"(b6), "=f"(b7)
                         : "r"(bAddr + k * (TN * 4) + 16));
            unsigned long long Bd[8];
            asm("mov.b64 %0,{%1,%1};" : "=l"(Bd[0]) : "f"(b0));
            asm("mov.b64 %0,{%1,%1};" : "=l"(Bd[1]) : "f"(b1));
            asm("mov.b64 %0,{%1,%1};" : "=l"(Bd[2]) : "f"(b2));
            asm("mov.b64 %0,{%1,%1};" : "=l"(Bd[3]) : "f"(b3));
            asm("mov.b64 %0,{%1,%1};" : "=l"(Bd[4]) : "f"(b4));
            asm("mov.b64 %0,{%1,%1};" : "=l"(Bd[5]) : "f"(b5));
            asm("mov.b64 %0,{%1,%1};" : "=l"(Bd[6]) : "f"(b6));
            asm("mov.b64 %0,{%1,%1};" : "=l"(Bd[7]) : "f"(b7));
#pragma unroll
            for (int j = 0; j < 8; j++) {
                FMA2(acc[0 * 8 + j], A0, Bd[j]);
                FMA2(acc[1 * 8 + j], A1, Bd[j]);
                FMA2(acc[2 * 8 + j], A2, Bd[j]);
                FMA2(acc[3 * 8 + j], A3, Bd[j]);
            }
        }

        // two 32-col chunks; threads with chunkq==q stage their 8 cols
#pragma unroll
        for (int q = 0; q < 2; q++) {
            if (chunkq == q) {
#pragma unroll
                for (int j = 0; j < 8; j++) {
                    float lo0, hi0, lo1, hi1, lo2, hi2, lo3, hi3;
                    asm("mov.b64 {%0,%1},%2;" : "=f"(lo0), "=f"(hi0) : "l"(acc[0 * 8 + j]));
                    asm("mov.b64 {%0,%1},%2;" : "=f"(lo1), "=f"(hi1) : "l"(acc[1 * 8 + j]));
                    asm("mov.b64 {%0,%1},%2;" : "=f"(lo2), "=f"(hi2) : "l"(acc[2 * 8 + j]));
                    asm("mov.b64 {%0,%1},%2;" : "=f"(lo3), "=f"(hi3) : "l"(acc[3 * 8 + j]));
                    float xc;
                    if (j == 0) xc = xq0.x; else if (j == 1) xc = xq0.y;
                    else if (j == 2) xc = xq0.z; else if (j == 3) xc = xq0.w;
                    else if (j == 4) xc = xq1.x; else if (j == 5) xc = xq1.y;
                    else if (j == 6) xc = xq1.z; else xc = xq1.w;
                    // EXACT score expression (matches reference noise):
                    float4 va = make_float4(2.f * lo0 - xra.x - xc, 2.f * hi0 - xra.y - xc,
                                            2.f * lo1 - xra.z - xc, 2.f * hi1 - xra.w - xc);
                    float4 vb = make_float4(2.f * lo2 - xrb.x - xc, 2.f * hi2 - xrb.y - xc,
                                            2.f * lo3 - xrb.z - xc, 2.f * hi3 - xrb.w - xc);
                    *(float4*)(Ss + (clcBase + j) * 128 + ra) = va;   // conflict-free
                    *(float4*)(Ss + (clcBase + j) * 128 + rb) = vb;
                }
            }
            __syncthreads();

            // scan: each thread scans its row over the 32 staged cols,
            // ascending column order (preserves lower-index-on-tie semantics)
            {
                const int cbase = col0 + q * 32;
#pragma unroll 4
                for (int j = 0; j < 32; j++) {
                    float s = Ss[j * 128 + tid];
                    if (s > sc[KK - 1]) {
                        int idv = cbase + j;
#pragma unroll
                        for (int p = KK - 1; p >= 1; --p) {
                            bool up  = s > sc[p - 1];
                            float ns = up ? sc[p - 1] : ((s > sc[p]) ? s   : sc[p]);
                            int   ni = up ? ix[p - 1] : ((s > sc[p]) ? idv : ix[p]);
                            sc[p] = ns; ix[p] = ni;
                        }
                        if (s > sc[0]) { sc[0] = s; ix[0] = idv; }
                    }
                }
            }
            __syncthreads();
        }
    }

    {
        size_t base = ((size_t)b * NN + row0 + tid) * KK;
#pragma unroll
        for (int p = 0; p < KK; p++) g_idx[base + p] = ix[p];
    }
}

// ---------------- fp64 exact rescoring of the 8 selected -> true order ----------------
__global__ void refine_kernel() {
    int b    = blockIdx.y;
    int n    = blockIdx.x * 8 + (threadIdx.x >> 5);
    int lane = threadIdx.x & 31;

    const float* ct = g_PT + ((size_t)b * NN + n) * CC;
    float cn[4];
#pragma unroll
    for (int i = 0; i < 4; i++) cn[i] = ct[lane + 32 * i];

    int* ip = g_idx + ((size_t)b * NN + n) * KK;
    double d[KK]; int id[KK];
#pragma unroll
    for (int k = 0; k < KK; k++) {
        int j = ip[k]; id[k] = j;
        const float* nt = g_PT + ((size_t)b * NN + j) * CC;
        double s = 0.0;
#pragma unroll
        for (int i = 0; i < 4; i++) {
            double df = (double)cn[i] - (double)nt[lane + 32 * i];
            s += df * df;
        }
#pragma unroll
        for (int o = 16; o > 0; o >>= 1) s += __shfl_xor_sync(0xffffffffu, s, o);
        d[k] = s;
    }

    if (lane == 0) {
        // insertion sort ascending by (d, idx): matches jax top_k ordering
        for (int a = 1; a < KK; a++) {
            double dv = d[a]; int iv = id[a]; int p = a - 1;
            while (p >= 0 && (d[p] > dv || (d[p] == dv && id[p] > iv))) {
                d[p + 1] = d[p]; id[p + 1] = id[p]; p--;
            }
            d[p + 1] = dv; id[p + 1] = iv;
        }
#pragma unroll
        for (int k = 0; k < KK; k++) ip[k] = id[k];
    }
}

// ---------------- G = conv2_w @ lrelu(points)  (per batch 128x4096x128) ----------------
__global__ void __launch_bounds__(256, 1) ggemm_kernel(const float* __restrict__ pts) {
    float* Ws = smem;              // [c][o] 128x128
    float* Fs = Ws + CC * CC;      // [c][n] 128x128
    const int tid = threadIdx.x;
    const int b = blockIdx.y;
    const int n0 = blockIdx.x * 128;
    const float* P = pts + (size_t)b * CC * NN;

    for (int i = tid; i < CC * CC / 4; i += 256)
        *(float4*)(Ws + i * 4) = *(const float4*)(g_WT + i * 4);
    for (int i = tid; i < CC * 128 / 4; i += 256) {
        int c = i >> 5; int n4 = (i & 31) << 2;
        float4 v = *(const float4*)(P + (size_t)c * NN + n0 + n4);
        v.x = lrelu(v.x); v.y = lrelu(v.y); v.z = lrelu(v.z); v.w = lrelu(v.w);
        *(float4*)(Fs + c * 128 + n4) = v;
    }
    __syncthreads();

    const int o0 = (tid & 15) * 8;
    const int m0 = (tid >> 4) * 8;
    float acc[8][8];
#pragma unroll
    for (int i = 0; i < 8; i++)
#pragma unroll
        for (int j = 0; j < 8; j++) acc[i][j] = 0.f;

#pragma unroll 2
    for (int k = 0; k < CC; k++) {
        float4 a0 = *(float4*)(Ws + k * CC + o0);
        float4 a1 = *(float4*)(Ws + k * CC + o0 + 4);
        float4 f0 = *(float4*)(Fs + k * 128 + m0);
        float4 f1 = *(float4*)(Fs + k * 128 + m0 + 4);
        float a[8] = { a0.x, a0.y, a0.z, a0.w, a1.x, a1.y, a1.z, a1.w };
        float f[8] = { f0.x, f0.y, f0.z, f0.w, f1.x, f1.y, f1.z, f1.w };
#pragma unroll
        for (int i = 0; i < 8; i++)
#pragma unroll
            for (int j = 0; j < 8; j++) acc[i][j] = fmaf(a[i], f[j], acc[i][j]);
    }

    float* Gp = g_G + (size_t)b * CC * NN;
#pragma unroll
    for (int i = 0; i < 8; i++) {
        float4 v0 = make_float4(acc[i][0], acc[i][1], acc[i][2], acc[i][3]);
        float4 v1 = make_float4(acc[i][4], acc[i][5], acc[i][6], acc[i][7]);
        *(float4*)(Gp + (size_t)(o0 + i) * NN + n0 + m0)     = v0;
        *(float4*)(Gp + (size_t)(o0 + i) * NN + n0 + m0 + 4) = v1;
    }
}

// ---------------- fused: out[b,c,n] and gnn[b,c,n,k] ----------------
// out = points + (lrelu(center) + sum_k lrelu(nbr))/9 ;  gnn = G[b,c,idx[b,n,k]]
__global__ void outgnn_kernel(const float* __restrict__ pts,
                              float* __restrict__ out, float* __restrict__ gnn) {
    __shared__ float prow[NN];
    __shared__ float grow[NN];
    int b = blockIdx.y, c = blockIdx.x;
    const float* P  = pts + ((size_t)b * CC + c) * NN;
    const float* Gp = g_G + ((size_t)b * CC + c) * NN;
    for (int i = threadIdx.x; i < NN / 4; i += 256) {
        *(float4*)(prow + i * 4) = *(const float4*)(P + i * 4);
        *(float4*)(grow + i * 4) = *(const float4*)(Gp + i * 4);
    }
    __syncthreads();
    float* gdst = gnn + ((size_t)b * CC + c) * NN * KK;
    for (int n = threadIdx.x; n < NN; n += 256) {
        const int4* ip = (const int4*)(g_idx + ((size_t)b * NN + n) * 8);
        int4 i0 = ip[0], i1 = ip[1];
        float x = prow[n];
        float s = lrelu(x);
        s += lrelu(prow[i0.x]); s += lrelu(prow[i0.y]); s += lrelu(prow[i0.z]); s += lrelu(prow[i0.w]);
        s += lrelu(prow[i1.x]); s += lrelu(prow[i1.y]); s += lrelu(prow[i1.z]); s += lrelu(prow[i1.w]);
        out[((size_t)b * CC + c) * NN + n] = x + s * (1.f / 9.f);
        float4 g0 = make_float4(grow[i0.x], grow[i0.y], grow[i0.z], grow[i0.w]);
        float4 g1 = make_float4(grow[i1.x], grow[i1.y], grow[i1.z], grow[i1.w]);
        *(float4*)(gdst + (size_t)n * KK)     = g0;
        *(float4*)(gdst + (size_t)n * KK + 4) = g1;
    }
}

// ---------------- launch ----------------
extern "C" void kernel_launch(void* const* d_in, const int* in_sizes, int n_in,
                              void* d_out, int out_size) {
    (void)in_sizes; (void)n_in; (void)out_size;
    const float* pts    = (const float*)d_in[0];
    // d_in[1] (W) is provably unused: mean(softmax) == 1/9 exactly.
    const float* conv2w = (const float*)d_in[2];
    float* out = (float*)d_out;
    float* gnn = out + (size_t)BB * CC * NN;

    cudaFuncSetAttribute(gram_topk_kernel, cudaFuncAttributeMaxDynamicSharedMemorySize, SMEM_FLOATS * 4);
    cudaFuncSetAttribute(ggemm_kernel,     cudaFuncAttributeMaxDynamicSharedMemorySize, 131072);

    xx_kernel<<<BB * NN / 256, 256>>>(pts);
    wt_kernel<<<CC * CC / 256, 256>>>(conv2w);
    pt_kernel<<<dim3(NN / 32, CC / 32, BB), dim3(32, 8)>>>(pts);
    gram_topk_kernel<<<dim3(NN / TM, BB), 128, SMEM_FLOATS * 4>>>(pts);
    refine_kernel<<<dim3(NN / 8, BB), 256>>>();
    ggemm_kernel<<<dim3(NN / 128, BB), 256, 131072>>>(pts);
    outgnn_kernel<<<dim3(CC, BB), 256>>>(pts, out, gnn);
}

// round 17
// speedup vs baseline: 1.4028x; 1.4001x over previous
#include <cuda_runtime.h>
#include <cstdint>

#define BB 8
#define CC 128
#define NN 4096
#define KK 8
#define TM 128
#define TN 64

// ---- device scratch (no allocations allowed) ----
__device__ float g_xx[BB * NN];
__device__ int   g_idx[BB * NN * KK];
__device__ float g_G[(size_t)BB * CC * NN];
__device__ float g_WT[CC * CC];
__device__ float g_PT[(size_t)BB * NN * CC];       // points transposed: [b][n][c]
__device__ unsigned char g_flag[BB * NN];          // 1 = row needs fp64 reorder

__device__ __forceinline__ float lrelu(float x) { return x > 0.f ? x : 0.01f * x; }

extern __shared__ __align__(16) float smem[];

// ---------------- xx[b,n] = sum_c points^2 ----------------
__global__ void xx_kernel(const float* __restrict__ pts) {
    int t = blockIdx.x * blockDim.x + threadIdx.x;   // b*N + n
    int b = t >> 12, n = t & (NN - 1);
    const float* p = pts + (size_t)b * CC * NN + n;
    float s = 0.f;
#pragma unroll
    for (int c = 0; c < CC; c++) { float v = p[(size_t)c * NN]; s = fmaf(v, v, s); }
    g_xx[t] = s;
}

// ---------------- transpose conv2_w -> g_WT[c][o] ----------------
__global__ void wt_kernel(const float* __restrict__ w) {
    int t = blockIdx.x * blockDim.x + threadIdx.x;   // o*128 + c
    int o = t >> 7, c = t & 127;
    g_WT[c * CC + o] = w[t];
}

// ---------------- transpose points -> g_PT[b][n][c] ----------------
__global__ void pt_kernel(const float* __restrict__ pts) {
    __shared__ float t[32][33];
    int b  = blockIdx.z;
    int c0 = blockIdx.y * 32, n0 = blockIdx.x * 32;
    for (int i = threadIdx.y; i < 32; i += 8)
        t[i][threadIdx.x] = pts[(size_t)b * CC * NN + (size_t)(c0 + i) * NN + n0 + threadIdx.x];
    __syncthreads();
    for (int i = threadIdx.y; i < 32; i += 8)
        g_PT[((size_t)b * NN + n0 + i) * CC + c0 + threadIdx.x] = t[threadIdx.x][i];
}

// ---------------- fused Gram + top-8 (the hot kernel) ----------------
// VERBATIM round-6 structure (measured 813us): 256 threads, thread = 4
// consecutive rows (lane) x cols {4w..4w+3, 32+4w..+3}. Per-(row,col) FFMA2
// accumulation chain over k and the score expression 2*inner - xr - xc are
// bit-identical to the verified kernel, so fp32 selection decisions match the
// reference's top_k at every row. Each 32-col chunk is staged by ALL 8 warps
// and scanned by ALL 256 threads (half-row partial top-8s, merged by
// (score desc, idx asc)). NEW (post-hoc only): write a per-row flag when the
// minimum adjacent gap of the merged top-8 scores is below 1e-2 — only those
// rows can need the fp64 reorder (score error bound ~3e-5, 300x margin).
#define FMA2(ACC, A, Bv) asm("fma.rn.f32x2 %0,%1,%2,%0;" : "+l"(ACC) : "l"(A), "l"(Bv))

#define SMEM_FLOATS (CC * TM + CC * TN + 32 * 128)   // 28672 floats = 112KB

__global__ void __launch_bounds__(256, 2) gram_topk_kernel(const float* __restrict__ pts) {
    float* As = smem;                 // [k][r] 128x128 = 64KB
    float* Bs = As + CC * TM;         // [k][c] 128x64  = 32KB
    float* Ss = Bs + CC * TN;         // [32][128] col-major chunk = 16KB (also merge scratch)

    const int tid  = threadIdx.x;
    const int lane = tid & 31;
    const int warp = tid >> 5;
    const int b    = blockIdx.y;
    const int row0 = blockIdx.x * TM;
    const float* P = pts + (size_t)b * CC * NN;

    // Load A tile once (coalesced, k-major, rows contiguous)
    for (int i = tid; i < CC * TM / 4; i += 256) {
        int k = i >> 5, r4 = (i & 31) << 2;
        *(float4*)(As + k * TM + r4) = *(const float4*)(P + (size_t)k * NN + row0 + r4);
    }

    // row norms for this thread's 4 staging rows
    float4 xrv = *(const float4*)(g_xx + b * NN + row0 + lane * 4);

    // per-thread sorted top-8 partial (thread t: row = t&127, col-half = t>>7)
    float sc[KK]; int ix[KK];
#pragma unroll
    for (int p = 0; p < KK; p++) { sc[p] = -3e38f; ix[p] = 0; }

    unsigned aAddr = (unsigned)__cvta_generic_to_shared(As) + lane * 16;
    unsigned bAddr = (unsigned)__cvta_generic_to_shared(Bs) + warp * 16;

    const int srow  = tid & 127;      // scanned row
    const int shalf = tid >> 7;       // scanned col half (0/1) within chunk

    for (int ct = 0; ct < NN / TN; ct++) {
        const int col0 = ct * TN;

        for (int i = tid; i < CC * TN / 4; i += 256) {
            int k = i >> 4, c4 = (i & 15) << 2;
            *(float4*)(Bs + k * TN + c4) = *(const float4*)(P + (size_t)k * NN + col0 + c4);
        }
        __syncthreads();

        // prefetch this thread's col norms (consumed at staging, hidden by compute)
        float4 xq0 = *(const float4*)(g_xx + b * NN + col0 + 4 * warp);
        float4 xq1 = *(const float4*)(g_xx + b * NN + col0 + 32 + 4 * warp);

        unsigned long long acc[16];   // acc[r*4+cp]: cp 0,1 -> cols 4w+2cp(+1); cp 2,3 -> cols 32+4w+2(cp-2)(+1)
#pragma unroll
        for (int i = 0; i < 16; i++) acc[i] = 0ULL;

#pragma unroll 4
        for (int k = 0; k < CC; k++) {
            float a0, a1, a2, a3;
            asm volatile("ld.shared.v4.b32 {%0,%1,%2,%3},[%4];"
                         : "=f"(a0), "=f"(a1), "=f"(a2), "=f"(a3)
                         : "r"(aAddr + k * (TM * 4)));
            unsigned long long B0, B1, B2, B3, A0, A1, A2, A3;
            asm volatile("ld.shared.v2.b64 {%0,%1},[%2];"
                         : "=l"(B0), "=l"(B1) : "r"(bAddr + k * (TN * 4)));
            asm volatile("ld.shared.v2.b64 {%0,%1},[%2];"
                         : "=l"(B2), "=l"(B3) : "r"(bAddr + k * (TN * 4) + 128));
            asm("mov.b64 %0,{%1,%1};" : "=l"(A0) : "f"(a0));
            asm("mov.b64 %0,{%1,%1};" : "=l"(A1) : "f"(a1));
            asm("mov.b64 %0,{%1,%1};" : "=l"(A2) : "f"(a2));
            asm("mov.b64 %0,{%1,%1};" : "=l"(A3) : "f"(a3));
            FMA2(acc[0],  A0, B0); FMA2(acc[1],  A0, B1); FMA2(acc[2],  A0, B2); FMA2(acc[3],  A0, B3);
            FMA2(acc[4],  A1, B0); FMA2(acc[5],  A1, B1); FMA2(acc[6],  A1, B2); FMA2(acc[7],  A1, B3);
            FMA2(acc[8],  A2, B0); FMA2(acc[9],  A2, B1); FMA2(acc[10], A2, B2); FMA2(acc[11], A2, B3);
            FMA2(acc[12], A3, B0); FMA2(acc[13], A3, B1); FMA2(acc[14], A3, B2); FMA2(acc[15], A3, B3);
        }

        // two 32-col chunks: q=0 -> cols [col0, col0+32) (cp 0,1),
        //                    q=1 -> cols [col0+32, col0+64) (cp 2,3)
#pragma unroll
        for (int q = 0; q < 2; q++) {
            // stage: every warp writes its 4 cols of this chunk (col-major [col][row])
#pragma unroll
            for (int cpp = 0; cpp < 2; cpp++) {
                int cp = q * 2 + cpp;
                float lo[4], hi[4];
#pragma unroll
                for (int r = 0; r < 4; r++)
                    asm("mov.b64 {%0,%1},%2;" : "=f"(lo[r]), "=f"(hi[r]) : "l"(acc[r * 4 + cp]));
                float xl, xh;
                if (q == 0) { xl = (cpp == 0) ? xq0.x : xq0.z; xh = (cpp == 0) ? xq0.y : xq0.w; }
                else        { xl = (cpp == 0) ? xq1.x : xq1.z; xh = (cpp == 0) ? xq1.y : xq1.w; }
                int cl = 4 * warp + 2 * cpp;
                // EXACT score expression (matches reference noise):
                float4 vlo = make_float4(2.f * lo[0] - xrv.x - xl, 2.f * lo[1] - xrv.y - xl,
                                         2.f * lo[2] - xrv.z - xl, 2.f * lo[3] - xrv.w - xl);
                float4 vhi = make_float4(2.f * hi[0] - xrv.x - xh, 2.f * hi[1] - xrv.y - xh,
                                         2.f * hi[2] - xrv.z - xh, 2.f * hi[3] - xrv.w - xh);
                *(float4*)(Ss + cl * 128 + lane * 4)       = vlo;   // conflict-free
                *(float4*)(Ss + (cl + 1) * 128 + lane * 4) = vhi;
            }
            __syncthreads();

            // scan: all 256 threads, thread scans 16 cols (its half) of its row,
            // ascending column order (preserves lower-index-on-tie semantics)
            {
                const int cbase = col0 + q * 32 + shalf * 16;
#pragma unroll 4
                for (int j = 0; j < 16; j++) {
                    float s = Ss[(shalf * 16 + j) * 128 + srow];
                    if (s > sc[KK - 1]) {
                        int idv = cbase + j;
#pragma unroll
                        for (int p = KK - 1; p >= 1; --p) {
                            bool up  = s > sc[p - 1];
                            float ns = up ? sc[p - 1] : ((s > sc[p]) ? s   : sc[p]);
                            int   ni = up ? ix[p - 1] : ((s > sc[p]) ? idv : ix[p]);
                            sc[p] = ns; ix[p] = ni;
                        }
                        if (s > sc[0]) { sc[0] = s; ix[0] = idv; }
                    }
                }
            }
            __syncthreads();
        }
    }

    // merge the two half-row partials by (score desc, idx asc) -> global top-8
    {
        float* msc = Ss;                       // [16][128]
        int*   mix = (int*)(Ss + 16 * 128);    // [16][128]
#pragma unroll
        for (int p = 0; p < KK; p++) {
            msc[(shalf * 8 + p) * 128 + srow] = sc[p];
            mix[(shalf * 8 + p) * 128 + srow] = ix[p];
        }
        __syncthreads();
        if (tid < TM) {
            int sel[KK]; float ssc[KK]; int i = 0, j = 0;
#pragma unroll
            for (int s = 0; s < KK; s++) {
                float av = msc[i * 128 + tid], bv = msc[(8 + j) * 128 + tid];
                int   ai = mix[i * 128 + tid], bi = mix[(8 + j) * 128 + tid];
                bool takeA = (av > bv) || (av == bv && ai < bi);
                sel[s] = takeA ? ai : bi;
                ssc[s] = takeA ? av : bv;
                if (takeA) i++; else j++;
            }
            size_t base = ((size_t)b * NN + row0 + tid) * KK;
#pragma unroll
            for (int p = 0; p < KK; p++) g_idx[base + p] = sel[p];

            // gap-gate: fp64 reorder can only matter where adjacent fp32 scores
            // are within noise (bound ~3e-5; threshold 1e-2 = 300x margin).
            float mg = 3e38f;
#pragma unroll
            for (int p = 0; p < KK - 1; p++) mg = fminf(mg, ssc[p] - ssc[p + 1]);
            g_flag[(size_t)b * NN + row0 + tid] = (mg < 1e-2f) ? 1 : 0;
        }
    }
}

// ---------------- fp64 exact rescoring of the 8 selected -> true order ----------------
// Only runs for rows flagged by the gap-gate (ambiguous fp32 ordering).
__global__ void refine_kernel() {
    int b    = blockIdx.y;
    int n    = blockIdx.x * 8 + (threadIdx.x >> 5);
    int lane = threadIdx.x & 31;

    if (g_flag[(size_t)b * NN + n] == 0) return;   // order already provably correct

    const float* ct = g_PT + ((size_t)b * NN + n) * CC;
    float cn[4];
#pragma unroll
    for (int i = 0; i < 4; i++) cn[i] = ct[lane + 32 * i];

    int* ip = g_idx + ((size_t)b * NN + n) * KK;
    double d[KK]; int id[KK];
#pragma unroll
    for (int k = 0; k < KK; k++) {
        int j = ip[k]; id[k] = j;
        const float* nt = g_PT + ((size_t)b * NN + j) * CC;
        double s = 0.0;
#pragma unroll
        for (int i = 0; i < 4; i++) {
            double df = (double)cn[i] - (double)nt[lane + 32 * i];
            s += df * df;
        }
#pragma unroll
        for (int o = 16; o > 0; o >>= 1) s += __shfl_xor_sync(0xffffffffu, s, o);
        d[k] = s;
    }

    if (lane == 0) {
        // insertion sort ascending by (d, idx): matches jax top_k ordering
        for (int a = 1; a < KK; a++) {
            double dv = d[a]; int iv = id[a]; int p = a - 1;
            while (p >= 0 && (d[p] > dv || (d[p] == dv && id[p] > iv))) {
                d[p + 1] = d[p]; id[p + 1] = id[p]; p--;
            }
            d[p + 1] = dv; id[p + 1] = iv;
        }
#pragma unroll
        for (int k = 0; k < KK; k++) ip[k] = id[k];
    }
}

// ---------------- G = conv2_w @ lrelu(points)  (per batch 128x4096x128) ----------------
__global__ void __launch_bounds__(256, 1) ggemm_kernel(const float* __restrict__ pts) {
    float* Ws = smem;              // [c][o] 128x128
    float* Fs = Ws + CC * CC;      // [c][n] 128x128
    const int tid = threadIdx.x;
    const int b = blockIdx.y;
    const int n0 = blockIdx.x * 128;
    const float* P = pts + (size_t)b * CC * NN;

    for (int i = tid; i < CC * CC / 4; i += 256)
        *(float4*)(Ws + i * 4) = *(const float4*)(g_WT + i * 4);
    for (int i = tid; i < CC * 128 / 4; i += 256) {
        int c = i >> 5; int n4 = (i & 31) << 2;
        float4 v = *(const float4*)(P + (size_t)c * NN + n0 + n4);
        v.x = lrelu(v.x); v.y = lrelu(v.y); v.z = lrelu(v.z); v.w = lrelu(v.w);
        *(float4*)(Fs + c * 128 + n4) = v;
    }
    __syncthreads();

    const int o0 = (tid & 15) * 8;
    const int m0 = (tid >> 4) * 8;
    float acc[8][8];
#pragma unroll
    for (int i = 0; i < 8; i++)
#pragma unroll
        for (int j = 0; j < 8; j++) acc[i][j] = 0.f;

#pragma unroll 2
    for (int k = 0; k < CC; k++) {
        float4 a0 = *(float4*)(Ws + k * CC + o0);
        float4 a1 = *(float4*)(Ws + k * CC + o0 + 4);
        float4 f0 = *(float4*)(Fs + k * 128 + m0);
        float4 f1 = *(float4*)(Fs + k * 128 + m0 + 4);
        float a[8] = { a0.x, a0.y, a0.z, a0.w, a1.x, a1.y, a1.z, a1.w };
        float f[8] = { f0.x, f0.y, f0.z, f0.w, f1.x, f1.y, f1.z, f1.w };
#pragma unroll
        for (int i = 0; i < 8; i++)
#pragma unroll
            for (int j = 0; j < 8; j++) acc[i][j] = fmaf(a[i], f[j], acc[i][j]);
    }

    float* Gp = g_G + (size_t)b * CC * NN;
#pragma unroll
    for (int i = 0; i < 8; i++) {
        float4 v0 = make_float4(acc[i][0], acc[i][1], acc[i][2], acc[i][3]);
        float4 v1 = make_float4(acc[i][4], acc[i][5], acc[i][6], acc[i][7]);
        *(float4*)(Gp + (size_t)(o0 + i) * NN + n0 + m0)     = v0;
        *(float4*)(Gp + (size_t)(o0 + i) * NN + n0 + m0 + 4) = v1;
    }
}

// ---------------- fused: out[b,c,n] and gnn[b,c,n,k] ----------------
// out = points + (lrelu(center) + sum_k lrelu(nbr))/9 ;  gnn = G[b,c,idx[b,n,k]]
__global__ void outgnn_kernel(const float* __restrict__ pts,
                              float* __restrict__ out, float* __restrict__ gnn) {
    __shared__ float prow[NN];
    __shared__ float grow[NN];
    int b = blockIdx.y, c = blockIdx.x;
    const float* P  = pts + ((size_t)b * CC + c) * NN;
    const float* Gp = g_G + ((size_t)b * CC + c) * NN;
    for (int i = threadIdx.x; i < NN / 4; i += 256) {
        *(float4*)(prow + i * 4) = *(const float4*)(P + i * 4);
        *(float4*)(grow + i * 4) = *(const float4*)(Gp + i * 4);
    }
    __syncthreads();
    float* gdst = gnn + ((size_t)b * CC + c) * NN * KK;
    for (int n = threadIdx.x; n < NN; n += 256) {
        const int4* ip = (const int4*)(g_idx + ((size_t)b * NN + n) * 8);
        int4 i0 = ip[0], i1 = ip[1];
        float x = prow[n];
        float s = lrelu(x);
        s += lrelu(prow[i0.x]); s += lrelu(prow[i0.y]); s += lrelu(prow[i0.z]); s += lrelu(prow[i0.w]);
        s += lrelu(prow[i1.x]); s += lrelu(prow[i1.y]); s += lrelu(prow[i1.z]); s += lrelu(prow[i1.w]);
        out[((size_t)b * CC + c) * NN + n] = x + s * (1.f / 9.f);
        float4 g0 = make_float4(grow[i0.x], grow[i0.y], grow[i0.z], grow[i0.w]);
        float4 g1 = make_float4(grow[i1.x], grow[i1.y], grow[i1.z], grow[i1.w]);
        *(float4*)(gdst + (size_t)n * KK)     = g0;
        *(float4*)(gdst + (size_t)n * KK + 4) = g1;
    }
}

// ---------------- launch ----------------
extern "C" void kernel_launch(void* const* d_in, const int* in_sizes, int n_in,
                              void* d_out, int out_size) {
    (void)in_sizes; (void)n_in; (void)out_size;
    const float* pts    = (const float*)d_in[0];
    // d_in[1] (W) is provably unused: mean(softmax) == 1/9 exactly.
    const float* conv2w = (const float*)d_in[2];
    float* out = (float*)d_out;
    float* gnn = out + (size_t)BB * CC * NN;

    cudaFuncSetAttribute(gram_topk_kernel, cudaFuncAttributeMaxDynamicSharedMemorySize, SMEM_FLOATS * 4);
    cudaFuncSetAttribute(ggemm_kernel,     cudaFuncAttributeMaxDynamicSharedMemorySize, 131072);

    xx_kernel<<<BB * NN / 256, 256>>>(pts);
    wt_kernel<<<CC * CC / 256, 256>>>(conv2w);
    pt_kernel<<<dim3(NN / 32, CC / 32, BB), dim3(32, 8)>>>(pts);
    gram_topk_kernel<<<dim3(NN / TM, BB), 256, SMEM_FLOATS * 4>>>(pts);
    refine_kernel<<<dim3(NN / 8, BB), 256>>>();
    ggemm_kernel<<<dim3(NN / 128, BB), 256, 131072>>>(pts);
    outgnn_kernel<<<dim3(CC, BB), 256>>>(pts, out, gnn);
}